// round 2
// baseline (speedup 1.0000x reference)
#include <cuda_runtime.h>

#define NB   4
#define IC   256
#define OC   128
#define IH   32
#define IW   88
#define NPIX (IH*IW)          // 2816
#define OW   496
#define OH   432

// Scratch (no cudaMalloc allowed): context after GEMM, and W-resized intermediate.
__device__ float g_ctx[NB*OC*NPIX];        // 4*128*2816 floats  = 5.77 MB
__device__ float g_tmp[NB*OC*IH*OW];       // 4*128*32*496 floats = 26 MB

// ---------------------------------------------------------------------------
// Kernel 1: ctx = (Wc[64:192] @ feat + bc[64:192]) / 64
// M=128 (all out channels), K=256, N=2816 per batch. Tile: 128x64, Kc=32.
// 256 threads, each computes an 8x4 register tile.
// ---------------------------------------------------------------------------
__global__ __launch_bounds__(256) void gemm_ctx_kernel(const float* __restrict__ feat,
                                                       const float* __restrict__ Wc,
                                                       const float* __restrict__ bc) {
    __shared__ __align__(16) float As[128][36];  // [m][k], padded row stride 36 (144B, 16B-mult)
    __shared__ __align__(16) float Bs[32][64];   // [k][n]

    const int tid = threadIdx.x;
    const int tx  = tid & 15;          // n-tile index 0..15
    const int ty  = tid >> 4;          // m-tile index 0..15
    const int m0  = ty * 8;
    const int n0  = tx * 4;
    const int b   = blockIdx.y;
    const int nb  = blockIdx.x * 64;   // pixel-tile base within batch

    const float* featB = feat + (size_t)b * IC * NPIX;

    float acc[8][4];
#pragma unroll
    for (int r = 0; r < 8; r++) {
        acc[r][0] = 0.f; acc[r][1] = 0.f; acc[r][2] = 0.f; acc[r][3] = 0.f;
    }

    for (int kt = 0; kt < IC; kt += 32) {
        // Load A tile: Wc rows 64..191, cols kt..kt+31  (1024 float4 by 256 threads)
#pragma unroll
        for (int l = 0; l < 4; l++) {
            int idx = l * 256 + tid;
            int m   = idx >> 3;
            int k4  = idx & 7;
            float4 v = *(const float4*)(Wc + (size_t)(64 + m) * IC + kt + k4 * 4);
            *(float4*)&As[m][k4 * 4] = v;
        }
        // Load B tile: feat[b, kt..kt+31, nb..nb+63] (512 float4 by 256 threads)
#pragma unroll
        for (int l = 0; l < 2; l++) {
            int idx = l * 256 + tid;
            int kk  = idx >> 4;
            int c4  = idx & 15;
            float4 v = *(const float4*)(featB + (size_t)(kt + kk) * NPIX + nb + c4 * 4);
            *(float4*)&Bs[kk][c4 * 4] = v;
        }
        __syncthreads();

#pragma unroll
        for (int k = 0; k < 32; k++) {
            float4 b4 = *(const float4*)&Bs[k][n0];
#pragma unroll
            for (int r = 0; r < 8; r++) {
                float a = As[m0 + r][k];   // broadcast across 16 lanes (2 addrs/warp)
                acc[r][0] += a * b4.x;
                acc[r][1] += a * b4.y;
                acc[r][2] += a * b4.z;
                acc[r][3] += a * b4.w;
            }
        }
        __syncthreads();
    }

    const float s = 1.0f / 64.0f;   // mean of softmax over 64 channels == 1/64 exactly
#pragma unroll
    for (int r = 0; r < 8; r++) {
        float bias = __ldg(bc + 64 + m0 + r);
        float4 o;
        o.x = (acc[r][0] + bias) * s;
        o.y = (acc[r][1] + bias) * s;
        o.z = (acc[r][2] + bias) * s;
        o.w = (acc[r][3] + bias) * s;
        *(float4*)&g_ctx[((size_t)(b * OC + m0 + r)) * NPIX + nb + n0] = o;
    }
}

// ---------------------------------------------------------------------------
// Kernel 2: separable bilinear, W pass: 88 -> 496 (half-pixel centers, edge clamp)
// tmp[p, h, j] = lerp over x of ctx[p, h, :]
// ---------------------------------------------------------------------------
__global__ __launch_bounds__(256) void resize_w_kernel() {
    int j = blockIdx.x * blockDim.x + threadIdx.x;
    if (j >= OW) return;
    int h = blockIdx.y;             // 0..31
    int p = blockIdx.z;             // 0..511  (b*128 + c)

    float x  = (j + 0.5f) * ((float)IW / (float)OW) - 0.5f;
    float xf = floorf(x);
    float wx = x - xf;
    int x0i  = (int)xf;
    int ix0  = min(IW - 1, max(0, x0i));
    int ix1  = min(IW - 1, max(0, x0i + 1));

    const float* row = g_ctx + ((size_t)p * IH + h) * IW;
    float v0 = row[ix0];
    float v1 = row[ix1];
    g_tmp[((size_t)p * IH + h) * OW + j] = v0 + wx * (v1 - v0);
}

// ---------------------------------------------------------------------------
// Kernel 3: H pass: 32 -> 432. Fully vectorized: 2x LDG.128 + 1x STG.128 per
// 4 outputs. This kernel writes the full 438.8 MB output -> HBM bound.
// ---------------------------------------------------------------------------
__global__ __launch_bounds__(512) void resize_h_kernel(float* __restrict__ out) {
    int tx = threadIdx.x;                 // 0..127, 124 used (496/4 float4 per row)
    if (tx >= OW / 4) return;
    int i = blockIdx.y * blockDim.y + threadIdx.y;  // 0..431
    int p = blockIdx.z;                             // 0..511

    float y  = (i + 0.5f) * ((float)IH / (float)OH) - 0.5f;
    float yf = floorf(y);
    float wy = y - yf;
    int y0i  = (int)yf;
    int y0   = min(IH - 1, max(0, y0i));
    int y1   = min(IH - 1, max(0, y0i + 1));

    const float4* r0 = (const float4*)(g_tmp + ((size_t)p * IH + y0) * OW);
    const float4* r1 = (const float4*)(g_tmp + ((size_t)p * IH + y1) * OW);
    float4 a = r0[tx];
    float4 b = r1[tx];
    float4 o;
    o.x = a.x + wy * (b.x - a.x);
    o.y = a.y + wy * (b.y - a.y);
    o.z = a.z + wy * (b.z - a.z);
    o.w = a.w + wy * (b.w - a.w);
    ((float4*)(out + ((size_t)p * OH + i) * OW))[tx] = o;
}

// ---------------------------------------------------------------------------
extern "C" void kernel_launch(void* const* d_in, const int* in_sizes, int n_in,
                              void* d_out, int out_size) {
    const float* feat = (const float*)d_in[0];   // [4,256,32,88]
    const float* Wc   = (const float*)d_in[1];   // [192,256]
    const float* bc   = (const float*)d_in[2];   // [192]
    float* out        = (float*)d_out;           // [4,128,432,496]

    // GEMM + bias + 1/64 scale -> g_ctx
    gemm_ctx_kernel<<<dim3(NPIX / 64, NB), 256>>>(feat, Wc, bc);

    // W-resize 88 -> 496 -> g_tmp
    resize_w_kernel<<<dim3((OW + 255) / 256, IH, NB * OC), 256>>>();

    // H-resize 32 -> 432 -> out (HBM-bound pass)
    resize_h_kernel<<<dim3(1, OH / 4, NB * OC), dim3(128, 4)>>>(out);
}

// round 3
// speedup vs baseline: 1.5871x; 1.5871x over previous
#include <cuda_runtime.h>

#define NB   4
#define IC   256
#define OC   128
#define IH   32
#define IW   88
#define NPIX (IH*IW)          // 2816
#define OW   496
#define OH   432
#define ROWS_PER_CHUNK 16
#define NCHUNK (OH / ROWS_PER_CHUNK)   // 27

// Scratch (no cudaMalloc allowed): context after GEMM.
__device__ float g_ctx[NB*OC*NPIX];        // 5.77 MB, L2-resident

// ---------------------------------------------------------------------------
// Kernel 1: ctx = (Wc[64:192] @ feat + bc[64:192]) / 64
// Softmax-mean over 64 channels is exactly 1/64, so depth branch is skipped.
// Tile: M=128 x N=32, Kc=32. 256 threads, each computes 8m x 2n.
// As stored transposed [k][m] so the inner loop reads 8 m's with 2 LDS.128.
// ---------------------------------------------------------------------------
__global__ __launch_bounds__(256) void gemm_ctx_kernel(const float* __restrict__ feat,
                                                       const float* __restrict__ Wc,
                                                       const float* __restrict__ bc) {
    __shared__ __align__(16) float As[32][132];  // [k][m], pad 132 (4-float skew)
    __shared__ __align__(16) float Bs[32][32];   // [k][n]

    const int tid = threadIdx.x;
    const int nh  = tid & 15;          // n-pair index
    const int ty  = tid >> 4;          // m-tile index 0..15
    const int m0  = ty * 8;
    const int n0  = nh * 2;
    const int b   = blockIdx.y;
    const int nb  = blockIdx.x * 32;   // pixel-tile base within batch

    const float* featB = feat + (size_t)b * IC * NPIX;

    float acc[8][2];
#pragma unroll
    for (int r = 0; r < 8; r++) { acc[r][0] = 0.f; acc[r][1] = 0.f; }

    for (int kt = 0; kt < IC; kt += 32) {
        // A tile: Wc rows 64..191, cols kt..kt+31 -> transposed into As[k][m]
#pragma unroll
        for (int l = 0; l < 4; l++) {
            int idx = l * 256 + tid;
            int m   = idx >> 3;
            int k4  = idx & 7;
            float4 v = *(const float4*)(Wc + (size_t)(64 + m) * IC + kt + k4 * 4);
            As[k4 * 4 + 0][m] = v.x;
            As[k4 * 4 + 1][m] = v.y;
            As[k4 * 4 + 2][m] = v.z;
            As[k4 * 4 + 3][m] = v.w;
        }
        // B tile: feat[b, kt..kt+31, nb..nb+31] (256 float4 by 256 threads)
        {
            int kk = tid >> 3;
            int c4 = tid & 7;
            float4 v = *(const float4*)(featB + (size_t)(kt + kk) * NPIX + nb + c4 * 4);
            *(float4*)&Bs[kk][c4 * 4] = v;
        }
        __syncthreads();

#pragma unroll
        for (int k = 0; k < 32; k++) {
            float4 a0 = *(const float4*)&As[k][m0];
            float4 a1 = *(const float4*)&As[k][m0 + 4];
            float2 bv = *(const float2*)&Bs[k][n0];
            acc[0][0] += a0.x * bv.x;  acc[0][1] += a0.x * bv.y;
            acc[1][0] += a0.y * bv.x;  acc[1][1] += a0.y * bv.y;
            acc[2][0] += a0.z * bv.x;  acc[2][1] += a0.z * bv.y;
            acc[3][0] += a0.w * bv.x;  acc[3][1] += a0.w * bv.y;
            acc[4][0] += a1.x * bv.x;  acc[4][1] += a1.x * bv.y;
            acc[5][0] += a1.y * bv.x;  acc[5][1] += a1.y * bv.y;
            acc[6][0] += a1.z * bv.x;  acc[6][1] += a1.z * bv.y;
            acc[7][0] += a1.w * bv.x;  acc[7][1] += a1.w * bv.y;
        }
        __syncthreads();
    }

    const float s = 1.0f / 64.0f;
#pragma unroll
    for (int r = 0; r < 8; r++) {
        float bias = __ldg(bc + 64 + m0 + r);
        float2 o;
        o.x = (acc[r][0] + bias) * s;
        o.y = (acc[r][1] + bias) * s;
        *(float2*)&g_ctx[((size_t)(b * OC + m0 + r)) * NPIX + nb + n0] = o;
    }
}

// ---------------------------------------------------------------------------
// Kernel 2: fused separable bilinear (32,88) -> (432,496), half-pixel + clamp.
// One CTA per (plane p, 16-output-row chunk). The 16 rows span <= 4 ctx rows:
// stage them in smem, W-interpolate into registers (4 float4/thread), then
// the 16-row store loop is pure FFMA + STG.128 (no smem, no gathers).
// ---------------------------------------------------------------------------
__global__ __launch_bounds__(128) void resize_fused_kernel(float* __restrict__ out) {
    const int p  = blockIdx.x;             // 0..511 (b*128 + c)
    const int i0 = blockIdx.y * ROWS_PER_CHUNK;
    const int tx = threadIdx.x;            // 0..127 (124 active for compute)

    __shared__ float raw[4][IW];

    const float sy = (float)IH / (float)OH;
    const float sx = (float)IW / (float)OW;

    float ymin = (i0 + 0.5f) * sy - 0.5f;
    int k0 = (int)floorf(ymin);

    // Stage 4 (clamped) ctx rows for this chunk.
    const float* base = g_ctx + (size_t)p * NPIX;
    for (int idx = tx; idx < 4 * IW; idx += 128) {
        int t = idx / IW;
        int j = idx - t * IW;
        int row = min(IH - 1, max(0, k0 + t));
        raw[t][j] = base[row * IW + j];
    }
    __syncthreads();

    if (tx >= OW / 4) return;

    // Per-thread W-interpolation setup for its 4 output columns.
    const int j0 = tx * 4;
    float wxv[4];
    int ia[4], ib[4];
#pragma unroll
    for (int q = 0; q < 4; q++) {
        float x  = (j0 + q + 0.5f) * sx - 0.5f;
        float xf = floorf(x);
        int x0i  = (int)xf;
        wxv[q]   = x - xf;
        ia[q]    = min(IW - 1, max(0, x0i));
        ib[q]    = min(IW - 1, max(0, x0i + 1));
    }

    // W-interpolate the 4 staged rows into registers.
    float4 r[4];
#pragma unroll
    for (int t = 0; t < 4; t++) {
        float v[4];
#pragma unroll
        for (int q = 0; q < 4; q++) {
            float a = raw[t][ia[q]];
            float b = raw[t][ib[q]];
            v[q] = a + wxv[q] * (b - a);
        }
        r[t] = make_float4(v[0], v[1], v[2], v[3]);
    }

    // Emit 16 output rows: pick the row pair via s = floor(y)-k0 in {0,1,2}.
    float4* outp = (float4*)(out + (size_t)p * OH * OW);
#pragma unroll
    for (int ii = 0; ii < ROWS_PER_CHUNK; ii++) {
        int i    = i0 + ii;
        float y  = (i + 0.5f) * sy - 0.5f;
        float yf = floorf(y);
        int s    = (int)yf - k0;           // 0..2 by span argument
        float wy = y - yf;
        float4 a = r[s];
        float4 bq = r[s + 1];
        float4 o;
        o.x = a.x + wy * (bq.x - a.x);
        o.y = a.y + wy * (bq.y - a.y);
        o.z = a.z + wy * (bq.z - a.z);
        o.w = a.w + wy * (bq.w - a.w);
        outp[(size_t)i * (OW / 4) + tx] = o;
    }
}

// ---------------------------------------------------------------------------
extern "C" void kernel_launch(void* const* d_in, const int* in_sizes, int n_in,
                              void* d_out, int out_size) {
    const float* feat = (const float*)d_in[0];   // [4,256,32,88]
    const float* Wc   = (const float*)d_in[1];   // [192,256]
    const float* bc   = (const float*)d_in[2];   // [192]
    float* out        = (float*)d_out;           // [4,128,432,496]

    // GEMM + bias + 1/64 scale -> g_ctx
    gemm_ctx_kernel<<<dim3(NPIX / 32, NB), 256>>>(feat, Wc, bc);

    // Fused bilinear resize -> out (HBM-store bound)
    resize_fused_kernel<<<dim3(NB * OC, NCHUNK), 128>>>(out);
}

// round 6
// speedup vs baseline: 1.6907x; 1.0652x over previous
#include <cuda_runtime.h>
#include <cstdint>

#define NB   4
#define IC   256
#define OC   128
#define IH   32
#define IW   88
#define NPIX (IH*IW)          // 2816
#define OW   496
#define OH   432
#define ROWS_PER_CHUNK 27
#define NCHUNK (OH / ROWS_PER_CHUNK)   // 16

// Scratch (no cudaMalloc allowed): context after GEMM. L2-resident (5.77 MB).
__device__ float g_ctx[NB*OC*NPIX];

// Packed fp32x2 helpers (base sm_100-family PTX, not 'a'-gated).
#define FFMA2(acc, a, b) \
    asm("fma.rn.f32x2 %0, %1, %2, %0;" : "+l"(acc) : "l"(a), "l"(b))
#define DUP_F32X2(out, v) \
    asm("mov.b64 %0, {%1, %1};" : "=l"(out) : "f"(v))
#define UNPACK_F32X2(lo, hi, in) \
    asm("mov.b64 {%0, %1}, %2;" : "=f"(lo), "=f"(hi) : "l"(in))

// ---------------------------------------------------------------------------
// Kernel 1: ctx = (Wc[64:192] @ feat + bc[64:192]) / 64
// (mean of softmax over 64 depth channels is exactly 1/64 -> depth branch gone)
// Tile M=128 x N=64, Kc=32. 256 threads, each 8m x 4n via 16 packed FFMA2.
// A pairs (m even/odd) come free from the 128-bit LDS; B scalars duplicated
// into both halves with one mov.b64 each.
// ---------------------------------------------------------------------------
__global__ __launch_bounds__(256) void gemm_ctx_kernel(const float* __restrict__ feat,
                                                       const float* __restrict__ Wc,
                                                       const float* __restrict__ bc) {
    __shared__ __align__(16) float As[32][132];  // [k][m], row 528B (16B mult)
    __shared__ __align__(16) float Bs[32][68];   // [k][n], row 272B (16B mult)

    const int tid = threadIdx.x;
    const int nh  = tid & 15;          // n-quad index 0..15
    const int ty  = tid >> 4;          // m-octet index 0..15
    const int m0  = ty * 8;
    const int n0  = nh * 4;
    const int b   = blockIdx.y;
    const int nb  = blockIdx.x * 64;   // pixel-tile base within batch

    const float* featB = feat + (size_t)b * IC * NPIX;

    unsigned long long acc[4][4];      // [m-pair][n], each = (f32 lo, f32 hi)
#pragma unroll
    for (int p = 0; p < 4; p++)
#pragma unroll
        for (int n = 0; n < 4; n++) acc[p][n] = 0ULL;

    for (int kt = 0; kt < IC; kt += 32) {
        // A tile: Wc rows 64..191, cols kt..kt+31, transposed into As[k][m]
#pragma unroll
        for (int l = 0; l < 4; l++) {
            int idx = l * 256 + tid;
            int m   = idx >> 3;
            int k4  = idx & 7;
            float4 v = *(const float4*)(Wc + (size_t)(64 + m) * IC + kt + k4 * 4);
            As[k4 * 4 + 0][m] = v.x;
            As[k4 * 4 + 1][m] = v.y;
            As[k4 * 4 + 2][m] = v.z;
            As[k4 * 4 + 3][m] = v.w;
        }
        // B tile: feat[b, kt..kt+31, nb..nb+63] (512 float4 by 256 threads)
#pragma unroll
        for (int l = 0; l < 2; l++) {
            int idx = l * 256 + tid;
            int kk  = idx >> 4;
            int c4  = idx & 15;
            float4 v = *(const float4*)(featB + (size_t)(kt + kk) * NPIX + nb + c4 * 4);
            *(float4*)&Bs[kk][c4 * 4] = v;
        }
        __syncthreads();

#pragma unroll
        for (int k = 0; k < 32; k++) {
            ulonglong2 a01 = *(const ulonglong2*)&As[k][m0];      // (m0,m0+1),(m0+2,m0+3)
            ulonglong2 a23 = *(const ulonglong2*)&As[k][m0 + 4];  // (m0+4,..),(m0+6,..)
            float4 bv = *(const float4*)&Bs[k][n0];
            unsigned long long bd0, bd1, bd2, bd3;
            DUP_F32X2(bd0, bv.x);
            DUP_F32X2(bd1, bv.y);
            DUP_F32X2(bd2, bv.z);
            DUP_F32X2(bd3, bv.w);
            FFMA2(acc[0][0], a01.x, bd0); FFMA2(acc[0][1], a01.x, bd1);
            FFMA2(acc[0][2], a01.x, bd2); FFMA2(acc[0][3], a01.x, bd3);
            FFMA2(acc[1][0], a01.y, bd0); FFMA2(acc[1][1], a01.y, bd1);
            FFMA2(acc[1][2], a01.y, bd2); FFMA2(acc[1][3], a01.y, bd3);
            FFMA2(acc[2][0], a23.x, bd0); FFMA2(acc[2][1], a23.x, bd1);
            FFMA2(acc[2][2], a23.x, bd2); FFMA2(acc[2][3], a23.x, bd3);
            FFMA2(acc[3][0], a23.y, bd0); FFMA2(acc[3][1], a23.y, bd1);
            FFMA2(acc[3][2], a23.y, bd2); FFMA2(acc[3][3], a23.y, bd3);
        }
        __syncthreads();
    }

    const float s = 1.0f / 64.0f;
#pragma unroll
    for (int p = 0; p < 4; p++) {
        float lo[4], hi[4];
#pragma unroll
        for (int n = 0; n < 4; n++) UNPACK_F32X2(lo[n], hi[n], acc[p][n]);

        int mlo = m0 + 2 * p;
        float blo = __ldg(bc + 64 + mlo);
        float bhi = __ldg(bc + 64 + mlo + 1);
        float4 olo, ohi;
        olo.x = (lo[0] + blo) * s; olo.y = (lo[1] + blo) * s;
        olo.z = (lo[2] + blo) * s; olo.w = (lo[3] + blo) * s;
        ohi.x = (hi[0] + bhi) * s; ohi.y = (hi[1] + bhi) * s;
        ohi.z = (hi[2] + bhi) * s; ohi.w = (hi[3] + bhi) * s;
        *(float4*)&g_ctx[((size_t)(b * OC + mlo)) * NPIX + nb + n0]     = olo;
        *(float4*)&g_ctx[((size_t)(b * OC + mlo + 1)) * NPIX + nb + n0] = ohi;
    }
}

// ---------------------------------------------------------------------------
// Kernel 2: fused separable bilinear (32,88) -> (432,496), half-pixel + clamp.
// One CTA per (plane, 27-output-row chunk); 27-row span covers <= 4 ctx rows.
// Stage 4 rows in smem, W-interp into registers, then 27 rows of pure
// FFMA + STG.128.
// ---------------------------------------------------------------------------
__global__ __launch_bounds__(128) void resize_fused_kernel(float* __restrict__ out) {
    const int p  = blockIdx.x;             // 0..511 (b*128 + c)
    const int i0 = blockIdx.y * ROWS_PER_CHUNK;
    const int tx = threadIdx.x;

    __shared__ float raw[4][IW];

    const float sy = (float)IH / (float)OH;
    const float sx = (float)IW / (float)OW;

    float ymin = (i0 + 0.5f) * sy - 0.5f;
    int k0 = (int)floorf(ymin);

    const float* base = g_ctx + (size_t)p * NPIX;
    for (int idx = tx; idx < 4 * IW; idx += 128) {
        int t = idx / IW;
        int j = idx - t * IW;
        int row = min(IH - 1, max(0, k0 + t));
        raw[t][j] = base[row * IW + j];
    }
    __syncthreads();

    if (tx >= OW / 4) return;

    const int j0 = tx * 4;
    float wxv[4];
    int ia[4], ib[4];
#pragma unroll
    for (int q = 0; q < 4; q++) {
        float x  = (j0 + q + 0.5f) * sx - 0.5f;
        float xf = floorf(x);
        int x0i  = (int)xf;
        wxv[q]   = x - xf;
        ia[q]    = min(IW - 1, max(0, x0i));
        ib[q]    = min(IW - 1, max(0, x0i + 1));
    }

    float4 r[4];
#pragma unroll
    for (int t = 0; t < 4; t++) {
        float v[4];
#pragma unroll
        for (int q = 0; q < 4; q++) {
            float a = raw[t][ia[q]];
            float b = raw[t][ib[q]];
            v[q] = a + wxv[q] * (b - a);
        }
        r[t] = make_float4(v[0], v[1], v[2], v[3]);
    }

    float4* outp = (float4*)(out + (size_t)p * OH * OW) + (size_t)i0 * (OW / 4) + tx;
#pragma unroll
    for (int ii = 0; ii < ROWS_PER_CHUNK; ii++) {
        float y  = (i0 + ii + 0.5f) * sy - 0.5f;
        float yf = floorf(y);
        int sidx = (int)yf - k0;           // 0..2 by span argument
        float wy = y - yf;
        float4 a  = r[sidx];
        float4 bq = r[sidx + 1];
        float4 o;
        o.x = a.x + wy * (bq.x - a.x);
        o.y = a.y + wy * (bq.y - a.y);
        o.z = a.z + wy * (bq.z - a.z);
        o.w = a.w + wy * (bq.w - a.w);
        __stcs(outp, o);
        outp += OW / 4;
    }
}

// ---------------------------------------------------------------------------
extern "C" void kernel_launch(void* const* d_in, const int* in_sizes, int n_in,
                              void* d_out, int out_size) {
    const float* feat = (const float*)d_in[0];   // [4,256,32,88]
    const float* Wc   = (const float*)d_in[1];   // [192,256]
    const float* bc   = (const float*)d_in[2];   // [192]
    float* out        = (float*)d_out;           // [4,128,432,496]

    gemm_ctx_kernel<<<dim3(NPIX / 64, NB), 256>>>(feat, Wc, bc);
    resize_fused_kernel<<<dim3(NB * OC, NCHUNK), 128>>>(out);
}